// round 4
// baseline (speedup 1.0000x reference)
#include <cuda_runtime.h>

#define Nn 4096
#define INSF 256
#define OUTF 64
#define NM 4
#define LEAKF 0.2f

// -------- scratch (device globals; no allocation allowed) --------
__device__ __align__(16) float g_h[NM * Nn * OUTF];        // 4 MB
__device__ __align__(16) float g_es[NM * Nn];
__device__ __align__(16) float g_ed[NM * Nn];
__device__ __align__(16) unsigned g_bits[(size_t)Nn * (Nn / 32)];  // 2 MB
__device__ __align__(16) float g_part[64 * INSF];
__device__ float g_gamma[NM * OUTF];
__device__ float g_beta[NM * OUTF];

// -------- 1) column partial sums for mean pool --------
__global__ void k_pool(const float* __restrict__ x) {
    int t = threadIdx.x;
    int r0 = blockIdx.x * 64;
    float s = 0.f;
    for (int r = 0; r < 64; ++r) s += x[(size_t)(r0 + r) * INSF + t];
    g_part[blockIdx.x * INSF + t] = s;
}

// -------- 2) finish pool + conditioner gb = pooled@Wc + bc -> gamma/beta --------
__global__ void k_cond(const float* __restrict__ Wc, const float* __restrict__ bc) {
    __shared__ float pooled[INSF];
    int t = threadIdx.x;
    if (t < INSF) {
        float s = 0.f;
        for (int b = 0; b < 64; ++b) s += g_part[b * INSF + t];
        pooled[t] = s * (1.0f / Nn);
    }
    __syncthreads();
    float s = bc[t];
    for (int i = 0; i < INSF; ++i) s += pooled[i] * Wc[i * (2 * NM * OUTF) + t];
    if (t < NM * OUTF) g_gamma[t] = s;
    else               g_beta[t - NM * OUTF] = s;
}

// -------- 3) pack adjacency into bitmask (read 64MB exactly once) --------
__global__ void k_pack(const int* __restrict__ adj) {
    size_t w = (size_t)blockIdx.x * blockDim.x + threadIdx.x;
    const int4* a = (const int4*)adj + w * 8;
    unsigned bits = 0;
#pragma unroll
    for (int q = 0; q < 8; ++q) {
        int4 v = a[q];
        bits |= (v.x ? 1u : 0u) << (q * 4 + 0);
        bits |= (v.y ? 1u : 0u) << (q * 4 + 1);
        bits |= (v.z ? 1u : 0u) << (q * 4 + 2);
        bits |= (v.w ? 1u : 0u) << (q * 4 + 3);
    }
    g_bits[w] = bits;
}

// -------- 4) h[m,n,o] = gamma[m,o]*(x[n,:]·W[m,:,o]) + beta[m,o] --------
__global__ void k_hgemm(const float* __restrict__ x, const float* __restrict__ W) {
    __shared__ float Xs[16][64];   // [k][row]
    __shared__ float Ws2[16][64];  // [k][o]
    int m = blockIdx.y;
    int n0 = blockIdx.x * 64;
    int t = threadIdx.x;
    int tx = t & 15, ty = t >> 4;
    float acc[4][4];
#pragma unroll
    for (int i = 0; i < 4; i++) {
#pragma unroll
        for (int j = 0; j < 4; j++) acc[i][j] = 0.f;
    }
    for (int k0 = 0; k0 < INSF; k0 += 16) {
        int row = t >> 2, kq = (t & 3) * 4;
        float4 xv = *(const float4*)&x[(size_t)(n0 + row) * INSF + k0 + kq];
        Xs[kq + 0][row] = xv.x; Xs[kq + 1][row] = xv.y;
        Xs[kq + 2][row] = xv.z; Xs[kq + 3][row] = xv.w;
        int kk = t >> 4, o4 = (t & 15) * 4;
        *(float4*)&Ws2[kk][o4] =
            *(const float4*)&W[(size_t)(m * INSF + k0 + kk) * OUTF + o4];
        __syncthreads();
#pragma unroll
        for (int kk2 = 0; kk2 < 16; ++kk2) {
            float xa[4], wb[4];
            *(float4*)xa = *(const float4*)&Xs[kk2][ty * 4];
            *(float4*)wb = *(const float4*)&Ws2[kk2][tx * 4];
#pragma unroll
            for (int i = 0; i < 4; i++) {
#pragma unroll
                for (int j = 0; j < 4; j++)
                    acc[i][j] = fmaf(xa[i], wb[j], acc[i][j]);
            }
        }
        __syncthreads();
    }
    int o4 = tx * 4;
    float4 gv = *(const float4*)&g_gamma[m * OUTF + o4];
    float4 bv = *(const float4*)&g_beta[m * OUTF + o4];
#pragma unroll
    for (int i = 0; i < 4; i++) {
        int n = n0 + ty * 4 + i;
        float4 hv;
        hv.x = gv.x * acc[i][0] + bv.x;
        hv.y = gv.y * acc[i][1] + bv.y;
        hv.z = gv.z * acc[i][2] + bv.z;
        hv.w = gv.w * acc[i][3] + bv.w;
        *(float4*)&g_h[((size_t)m * Nn + n) * OUTF + o4] = hv;
    }
}

// -------- 5) e_src/e_dst: one warp per (m,n), dot h with a1/a2 --------
__global__ void k_ea(const float* __restrict__ a1, const float* __restrict__ a2) {
    int gt = blockIdx.x * 256 + threadIdx.x;
    int wid = gt >> 5, lane = gt & 31;
    int m = wid >> 12, n = wid & (Nn - 1);
    const float* hrow = g_h + ((size_t)m * Nn + n) * OUTF;
    float h0 = hrow[lane], h1 = hrow[32 + lane];
    float s1 = h0 * a1[m * OUTF + lane] + h1 * a1[m * OUTF + 32 + lane];
    float s2 = h0 * a2[m * OUTF + lane] + h1 * a2[m * OUTF + 32 + lane];
#pragma unroll
    for (int s = 16; s > 0; s >>= 1) {
        s1 += __shfl_xor_sync(0xffffffffu, s1, s);
        s2 += __shfl_xor_sync(0xffffffffu, s2, s);
    }
    if (lane == 0) { g_es[wid] = s1; g_ed[wid] = s2; }
}

// -------- 6) main fused masked-softmax attention: out = softmax(P)@H, elu --------
// Grid (Nn/128, NM). Row-max precomputed via bit-scan (lrelu monotone => exact).
__global__ __launch_bounds__(256, 1)
void k_main(float* __restrict__ out) {
    extern __shared__ float sm[];
    float* ed_s = sm;                            // 4096
    float* Hs = sm + 4096;                       // 128*64
    float* Ps = sm + 4096 + 8192;                // 128*128
    float* es_s = sm + 4096 + 8192 + 16384;      // 128
    float* md_s = es_s + 128;                    // 128
    float* den_s = md_s + 128;                   // 256
    unsigned* bits_s = (unsigned*)(den_s + 256); // 512 words

    int m = blockIdx.y;
    int i0 = blockIdx.x * 128;
    int t = threadIdx.x;

    {
        const float4* src = (const float4*)(g_ed + (size_t)m * Nn);
        float4* dst = (float4*)ed_s;
        for (int q = t; q < Nn / 4; q += 256) dst[q] = src[q];
    }
    if (t < 128) es_s[t] = g_es[(size_t)m * Nn + i0 + t];
    __syncthreads();

    // phase 1: md[r] = max over neighbors j of ed[m,j]
    {
        int warp = t >> 5, lane = t & 31;
        for (int rr = 0; rr < 16; ++rr) {
            int r = warp * 16 + rr;
            const unsigned* brow = g_bits + (size_t)(i0 + r) * (Nn / 32);
            float mx = -1e30f;
            for (int w = lane; w < Nn / 32; w += 32) {
                unsigned b = brow[w];
                while (b) {
                    int j = __ffs(b) - 1;
                    b &= b - 1;
                    mx = fmaxf(mx, ed_s[w * 32 + j]);
                }
            }
#pragma unroll
            for (int s = 16; s > 0; s >>= 1)
                mx = fmaxf(mx, __shfl_xor_sync(0xffffffffu, mx, s));
            if (lane == 0) md_s[r] = mx;
        }
    }

    float acc[8][4];
#pragma unroll
    for (int i = 0; i < 8; i++) {
#pragma unroll
        for (int j = 0; j < 4; j++) acc[i][j] = 0.f;
    }
    float dloc = 0.f;

    int rowg = t >> 4, colg = t & 15;
    int rbase = rowg * 8, cbase = colg * 4;
    int rp = t >> 1, half = t & 1;

    for (int jt = 0; jt < Nn / 128; ++jt) {
        int j0 = jt * 128;
        __syncthreads();
        {
            const float4* src = (const float4*)(g_h + ((size_t)m * Nn + j0) * OUTF);
            float4* dst = (float4*)Hs;
            for (int q = t; q < 128 * OUTF / 4; q += 256) dst[q] = src[q];
            for (int q = t; q < 512; q += 256)
                bits_s[q] = g_bits[(size_t)(i0 + (q >> 2)) * (Nn / 32) + (j0 >> 5) + (q & 3)];
        }
        __syncthreads();
        {
            float esr = es_s[rp], mdr = md_s[rp];
            int jb = half * 64;
            unsigned wa = bits_s[rp * 4 + half * 2 + 0];
            unsigned wb = bits_s[rp * 4 + half * 2 + 1];
#pragma unroll
            for (int k = 0; k < 32; ++k) {
                float v = esr + ed_s[j0 + jb + k];
                v = v > 0.f ? v : LEAKF * v;
                float p = ((wa >> k) & 1u) ? __expf(v - mdr) : 0.f;
                Ps[(jb + k) * 128 + rp] = p;
                dloc += p;
            }
#pragma unroll
            for (int k = 0; k < 32; ++k) {
                float v = esr + ed_s[j0 + jb + 32 + k];
                v = v > 0.f ? v : LEAKF * v;
                float p = ((wb >> k) & 1u) ? __expf(v - mdr) : 0.f;
                Ps[(jb + 32 + k) * 128 + rp] = p;
                dloc += p;
            }
        }
        __syncthreads();
#pragma unroll 2
        for (int jj = 0; jj < 128; ++jj) {
            float pr[8], hv[4];
            *(float4*)&pr[0] = *(const float4*)(Ps + jj * 128 + rbase);
            *(float4*)&pr[4] = *(const float4*)(Ps + jj * 128 + rbase + 4);
            *(float4*)&hv[0] = *(const float4*)(Hs + jj * OUTF + cbase);
#pragma unroll
            for (int i = 0; i < 8; i++) {
#pragma unroll
                for (int j = 0; j < 4; j++)
                    acc[i][j] = fmaf(pr[i], hv[j], acc[i][j]);
            }
        }
    }
    den_s[t] = dloc;
    __syncthreads();
#pragma unroll
    for (int i = 0; i < 8; i++) {
        int r = rbase + i;
        float inv = 1.0f / (den_s[2 * r] + den_s[2 * r + 1]);
        float4 o;
        float v;
        v = acc[i][0] * inv; o.x = v > 0.f ? v : __expf(v) - 1.f;
        v = acc[i][1] * inv; o.y = v > 0.f ? v : __expf(v) - 1.f;
        v = acc[i][2] * inv; o.z = v > 0.f ? v : __expf(v) - 1.f;
        v = acc[i][3] * inv; o.w = v > 0.f ? v : __expf(v) - 1.f;
        *(float4*)&out[(size_t)(i0 + r) * (NM * OUTF) + m * OUTF + cbase] = o;
    }
}

extern "C" void kernel_launch(void* const* d_in, const int* in_sizes, int n_in,
                              void* d_out, int out_size) {
    const float* x   = (const float*)d_in[0];
    const int*   adj = (const int*)d_in[1];
    const float* W   = (const float*)d_in[2];
    const float* a1  = (const float*)d_in[3];
    const float* a2  = (const float*)d_in[4];
    const float* Wc  = (const float*)d_in[5];
    const float* bc  = (const float*)d_in[6];
    float* out = (float*)d_out;

    cudaFuncSetAttribute(k_main, cudaFuncAttributeMaxDynamicSharedMemorySize, 118784);

    k_pool<<<64, 256>>>(x);
    k_cond<<<1, 512>>>(Wc, bc);
    k_pack<<<2048, 256>>>(adj);                 // 4096*4096/32 = 524288 words
    k_hgemm<<<dim3(Nn / 64, NM), 256>>>(x, W);
    k_ea<<<NM * Nn / 8, 256>>>(a1, a2);
    k_main<<<dim3(Nn / 128, NM), 256, 118784>>>(out);
}

// round 16
// speedup vs baseline: 2.7416x; 2.7416x over previous
#include <cuda_runtime.h>
#include <cuda_fp16.h>
#include <cstdint>

#define Nn 4096
#define INSF 256
#define OUTF 64
#define NM 4

// -------- scratch (device globals; no allocation allowed) --------
__device__ __align__(16) float   g_h [NM * Nn * OUTF];          // 4 MB fp32
__device__ __align__(16) __half  g_hT[(size_t)NM * OUTF * Nn];  // 2 MB fp16 [m][o][j]
__device__ __align__(16) float   g_es[NM * Nn];
__device__ __align__(16) float   g_ed[NM * Nn];
__device__ __align__(16) unsigned g_bits[(size_t)Nn * (Nn / 32)];
__device__ __align__(16) float   g_part[64 * INSF];
__device__ float g_gamma[NM * OUTF];
__device__ float g_beta[NM * OUTF];

__device__ __forceinline__ uint32_t smem_u32(const void* p) {
    uint32_t a;
    asm("{ .reg .u64 t; cvta.to.shared.u64 t, %1; cvt.u32.u64 %0, t; }" : "=r"(a) : "l"(p));
    return a;
}

__device__ __forceinline__ void ldm_x4(uint32_t& r0, uint32_t& r1, uint32_t& r2, uint32_t& r3,
                                       uint32_t addr) {
    asm volatile("ldmatrix.sync.aligned.m8n8.x4.shared.b16 {%0,%1,%2,%3}, [%4];"
                 : "=r"(r0), "=r"(r1), "=r"(r2), "=r"(r3) : "r"(addr));
}

__device__ __forceinline__ void mma16816(float* d, uint32_t a0, uint32_t a1, uint32_t a2,
                                         uint32_t a3, uint32_t b0, uint32_t b1) {
    asm volatile(
        "mma.sync.aligned.m16n8k16.row.col.f32.f16.f16.f32 "
        "{%0,%1,%2,%3}, {%4,%5,%6,%7}, {%8,%9}, {%0,%1,%2,%3};"
        : "+f"(d[0]), "+f"(d[1]), "+f"(d[2]), "+f"(d[3])
        : "r"(a0), "r"(a1), "r"(a2), "r"(a3), "r"(b0), "r"(b1));
}

// p = mask ? exp((lrelu(ed+es) - md)) : 0   (all fp16x2, exp via exp2)
__device__ __forceinline__ uint32_t pe_pair(uint32_t edu, __half2 esr, __half2 c2r,
                                            uint32_t b2, __half2 k02, __half2 klg) {
    __half2 ed2 = *reinterpret_cast<__half2*>(&edu);
    __half2 t1 = __hadd2(ed2, esr);
    __half2 v = __hmax2(t1, __hmul2(t1, k02));
    __half2 arg = __hfma2(v, klg, c2r);
    __half2 p = h2exp2(arg);
    uint32_t mv = (b2 & 1u) * 0x3C00u + (b2 & 2u) * 0x1E000000u;
    __half2 mh = *reinterpret_cast<__half2*>(&mv);
    __half2 r = __hmul2(p, mh);
    return *reinterpret_cast<uint32_t*>(&r);
}

// ---------------- 1) column partial sums for mean pool ----------------
__global__ void k_pool(const float* __restrict__ x) {
    int t = threadIdx.x;
    int r0 = blockIdx.x * 64;
    float s = 0.f;
    for (int r = 0; r < 64; ++r) s += x[(size_t)(r0 + r) * INSF + t];
    g_part[blockIdx.x * INSF + t] = s;
}

// ---------------- 2) conditioner ----------------
__global__ void k_cond(const float* __restrict__ Wc, const float* __restrict__ bc) {
    __shared__ float pooled[INSF];
    int t = threadIdx.x;
    if (t < INSF) {
        float s = 0.f;
        for (int b = 0; b < 64; ++b) s += g_part[b * INSF + t];
        pooled[t] = s * (1.0f / Nn);
    }
    __syncthreads();
    float s = bc[t];
    for (int i = 0; i < INSF; ++i) s += pooled[i] * Wc[i * (2 * NM * OUTF) + t];
    if (t < NM * OUTF) g_gamma[t] = s;
    else               g_beta[t - NM * OUTF] = s;
}

// ---------------- 3) pack adjacency to bitmask ----------------
__global__ void k_pack(const int* __restrict__ adj) {
    size_t w = (size_t)blockIdx.x * blockDim.x + threadIdx.x;
    const int4* a = (const int4*)adj + w * 8;
    unsigned bits = 0;
#pragma unroll
    for (int q = 0; q < 8; ++q) {
        int4 v = a[q];
        bits |= (v.x ? 1u : 0u) << (q * 4 + 0);
        bits |= (v.y ? 1u : 0u) << (q * 4 + 1);
        bits |= (v.z ? 1u : 0u) << (q * 4 + 2);
        bits |= (v.w ? 1u : 0u) << (q * 4 + 3);
    }
    g_bits[w] = bits;
}

// ---------------- 4) h = FiLM(x@W) : two mechanisms per block ----------------
__global__ void k_hgemm(const float* __restrict__ x, const float* __restrict__ W) {
    __shared__ float Xs[16][64];
    __shared__ float Wa[16][64];
    __shared__ float Wb[16][64];
    int m0 = blockIdx.y * 2;
    int n0 = blockIdx.x * 64;
    int t = threadIdx.x;
    int tx = t & 15, ty = t >> 4;
    float acc[2][4][4];
#pragma unroll
    for (int mm = 0; mm < 2; mm++)
#pragma unroll
        for (int i = 0; i < 4; i++)
#pragma unroll
            for (int j = 0; j < 4; j++) acc[mm][i][j] = 0.f;

    for (int k0 = 0; k0 < INSF; k0 += 16) {
        int row = t >> 2, kq = (t & 3) * 4;
        float4 xv = *(const float4*)&x[(size_t)(n0 + row) * INSF + k0 + kq];
        Xs[kq + 0][row] = xv.x; Xs[kq + 1][row] = xv.y;
        Xs[kq + 2][row] = xv.z; Xs[kq + 3][row] = xv.w;
        int kk = t >> 4, o4 = (t & 15) * 4;
        *(float4*)&Wa[kk][o4] = *(const float4*)&W[(size_t)((m0 + 0) * INSF + k0 + kk) * OUTF + o4];
        *(float4*)&Wb[kk][o4] = *(const float4*)&W[(size_t)((m0 + 1) * INSF + k0 + kk) * OUTF + o4];
        __syncthreads();
#pragma unroll
        for (int kk2 = 0; kk2 < 16; ++kk2) {
            float xa[4], wva[4], wvb[4];
            *(float4*)xa  = *(const float4*)&Xs[kk2][ty * 4];
            *(float4*)wva = *(const float4*)&Wa[kk2][tx * 4];
            *(float4*)wvb = *(const float4*)&Wb[kk2][tx * 4];
#pragma unroll
            for (int i = 0; i < 4; i++)
#pragma unroll
                for (int j = 0; j < 4; j++) {
                    acc[0][i][j] = fmaf(xa[i], wva[j], acc[0][i][j]);
                    acc[1][i][j] = fmaf(xa[i], wvb[j], acc[1][i][j]);
                }
        }
        __syncthreads();
    }
    int o4 = tx * 4;
#pragma unroll
    for (int mm = 0; mm < 2; mm++) {
        int m = m0 + mm;
        float4 gv = *(const float4*)&g_gamma[m * OUTF + o4];
        float4 bv = *(const float4*)&g_beta[m * OUTF + o4];
#pragma unroll
        for (int i = 0; i < 4; i++) {
            int n = n0 + ty * 4 + i;
            float4 hv;
            hv.x = gv.x * acc[mm][i][0] + bv.x;
            hv.y = gv.y * acc[mm][i][1] + bv.y;
            hv.z = gv.z * acc[mm][i][2] + bv.z;
            hv.w = gv.w * acc[mm][i][3] + bv.w;
            *(float4*)&g_h[((size_t)m * Nn + n) * OUTF + o4] = hv;
        }
    }
}

// ---------------- 5) e_src/e_dst ----------------
__global__ void k_ea(const float* __restrict__ a1, const float* __restrict__ a2) {
    int gt = blockIdx.x * 256 + threadIdx.x;
    int wid = gt >> 5, lane = gt & 31;
    int m = wid >> 12, n = wid & (Nn - 1);
    const float* hrow = g_h + ((size_t)m * Nn + n) * OUTF;
    float h0 = hrow[lane], h1 = hrow[32 + lane];
    float s1 = h0 * a1[m * OUTF + lane] + h1 * a1[m * OUTF + 32 + lane];
    float s2 = h0 * a2[m * OUTF + lane] + h1 * a2[m * OUTF + 32 + lane];
#pragma unroll
    for (int s = 16; s > 0; s >>= 1) {
        s1 += __shfl_xor_sync(0xffffffffu, s1, s);
        s2 += __shfl_xor_sync(0xffffffffu, s2, s);
    }
    if (lane == 0) { g_es[wid] = s1; g_ed[wid] = s2; }
}

// ---------------- 5b) transpose h -> fp16 [m][o][j] ----------------
__global__ void k_tr() {
    __shared__ float s[64][65];
    int m = blockIdx.y, j0 = blockIdx.x * 64, t = threadIdx.x;
    for (int u = t; u < 4096; u += 256) {
        int j = u >> 6, o = u & 63;
        s[j][o] = g_h[((size_t)m * Nn + j0 + j) * OUTF + o];
    }
    __syncthreads();
    for (int v = t; v < 2048; v += 256) {
        int o = v >> 5, jw = v & 31;
        __half2 hv = __floats2half2_rn(s[jw * 2][o], s[jw * 2 + 1][o]);
        *(__half2*)&g_hT[((size_t)(m * OUTF + o)) * Nn + j0 + jw * 2] = hv;
    }
}

// ---------------- 6) mma.sync masked-softmax attention ----------------
// CTA: (i-tile of 128, mechanism m). 8 warps x 16 rows. 32 stages of 128 j,
// double-buffered H^T in smem; per chunk of 16 j: A=P built in mma register
// layout, B via ldmatrix, 8 n-group mma + 1 ones-column mma (denominator).
#define SED 0
#define SES 8192
#define SC2 8704
#define SHS 9216
#define HSB 17408               // 64 rows * 272B (272 = 256 + 16 pad, conflict-free ldmatrix)
#define SMTOT (SHS + 2 * HSB)   // 44032 < 48KB static limit

__global__ __launch_bounds__(256, 1) void k_attn(float* __restrict__ out) {
    __shared__ __align__(16) char smem[SMTOT];
    const uint32_t sb = smem_u32(smem);
    int t = threadIdx.x;
    int wid = t >> 5, lane = t & 31;
    int m = blockIdx.y;
    int i0 = blockIdx.x * 128;

    // --- prologue: ed fp32 (temp in Hs area), row-max bit-scan, fp16 tables ---
    float* edf = (float*)(smem + SHS);
    {
        const float4* src = (const float4*)(g_ed + (size_t)m * Nn);
        float4* dst = (float4*)edf;
        for (int q = t; q < Nn / 4; q += 256) dst[q] = src[q];
    }
    __syncthreads();

    float* mdf = (float*)(smem + SC2);
    for (int rr = 0; rr < 16; ++rr) {
        int r = wid * 16 + rr;
        const unsigned* brow = g_bits + (size_t)(i0 + r) * (Nn / 32);
        float mx = -1e30f;
        for (int w = lane; w < Nn / 32; w += 32) {
            unsigned b = brow[w];
            while (b) {
                int j = __ffs(b) - 1;
                b &= b - 1;
                mx = fmaxf(mx, edf[w * 32 + j]);
            }
        }
#pragma unroll
        for (int s = 16; s > 0; s >>= 1)
            mx = fmaxf(mx, __shfl_xor_sync(0xffffffffu, mx, s));
        if (lane == 0) mdf[r] = mx;
    }
    __half2* ed2s = (__half2*)(smem + SED);
    for (int q = t; q < Nn / 2; q += 256)
        ed2s[q] = __floats2half2_rn(edf[2 * q], edf[2 * q + 1]);
    float* esf = (float*)(smem + SES);
    if (t < 128) esf[t] = g_es[(size_t)m * Nn + i0 + t];
    __syncthreads();
    float* c2f = (float*)(smem + SC2);
    if (t < 128) c2f[t] = -mdf[t] * 1.4426950408889634f;
    __syncthreads();   // also: all edf reads done before Hs staging overwrites it

    // --- per-thread constants (mma fragment rows r and r+8) ---
    int r = (wid << 4) + (lane >> 2);
    __half2 esr  = __float2half2_rn(esf[r]);
    __half2 esr8 = __float2half2_rn(esf[r + 8]);
    __half2 c2r  = __float2half2_rn(c2f[r]);
    __half2 c2r8 = __float2half2_rn(c2f[r + 8]);
    const __half2 k02 = __float2half2_rn(0.2f);
    const __half2 klg = __float2half2_rn(1.4426950408889634f);
    uint32_t bden = (lane < 4) ? 0x3C003C00u : 0u;   // ones column n=0

    float d[8][4];
    float dd[4] = {0.f, 0.f, 0.f, 0.f};
#pragma unroll
    for (int g = 0; g < 8; ++g)
#pragma unroll
        for (int k = 0; k < 4; ++k) d[g][k] = 0.f;

    const __half* hTm = g_hT + (size_t)m * OUTF * Nn;
    const unsigned* bitsr  = g_bits + (size_t)(i0 + r) * (Nn / 32);
    const unsigned* bitsr8 = g_bits + (size_t)(i0 + r + 8) * (Nn / 32);
    int so = (t >> 4);          // row o this thread stages (u = t + 256k -> o = u>>4)
    int sjq = (t & 15);         // uint4 index within 128-j row segment

    // stage 0 load
    uint4 mr  = *(const uint4*)(bitsr);
    uint4 mr8 = *(const uint4*)(bitsr8);
    {
#pragma unroll
        for (int k = 0; k < 4; ++k) {
            int o = so + k * 16;
            uint4 v = *(const uint4*)(hTm + (size_t)o * Nn + sjq * 8);
            *(uint4*)(smem + SHS + o * 272 + sjq * 16) = v;
        }
    }
    __syncthreads();

    for (int s = 0; s < 32; ++s) {
        uint32_t cb = sb + SHS + (uint32_t)(s & 1) * HSB;
        uint32_t nboff = SHS + (uint32_t)((s + 1) & 1) * HSB;
        uint4 nr[4], nmr, nmr8;
        if (s < 31) {
#pragma unroll
            for (int k = 0; k < 4; ++k)
                nr[k] = *(const uint4*)(hTm + (size_t)(so + k * 16) * Nn + (s + 1) * 128 + sjq * 8);
            nmr  = *(const uint4*)(bitsr  + (s + 1) * 4);
            nmr8 = *(const uint4*)(bitsr8 + (s + 1) * 4);
        }
        uint32_t mwr[4]  = {mr.x, mr.y, mr.z, mr.w};
        uint32_t mwr8[4] = {mr8.x, mr8.y, mr8.z, mr8.w};
#pragma unroll
        for (int c = 0; c < 8; ++c) {
            // A fragments (P)
            int e0 = s * 64 + c * 8 + (lane & 3);
            uint32_t edlo = *(uint32_t*)&ed2s[e0];
            uint32_t edhi = *(uint32_t*)&ed2s[e0 + 4];
            uint32_t wlo  = mwr[c >> 1]  >> ((c & 1) * 16);
            uint32_t wlo8 = mwr8[c >> 1] >> ((c & 1) * 16);
            int q = (lane & 3) * 2;
            uint32_t a0 = pe_pair(edlo, esr,  c2r,  (wlo  >> q) & 3u, k02, klg);
            uint32_t a1 = pe_pair(edlo, esr8, c2r8, (wlo8 >> q) & 3u, k02, klg);
            uint32_t a2 = pe_pair(edhi, esr,  c2r,  (wlo  >> (q + 8)) & 3u, k02, klg);
            uint32_t a3 = pe_pair(edhi, esr8, c2r8, (wlo8 >> (q + 8)) & 3u, k02, klg);
            // B fragments (H^T) via ldmatrix: 16 8x8 matrices
            uint32_t bf[16];
#pragma unroll
            for (int q4 = 0; q4 < 4; ++q4) {
                int mi = q4 * 4 + (lane >> 3);
                uint32_t addr = cb + (uint32_t)(((mi >> 1) * 8 + (lane & 7)) * 272
                                                + (c * 16 + (mi & 1) * 8) * 2);
                ldm_x4(bf[q4 * 4 + 0], bf[q4 * 4 + 1], bf[q4 * 4 + 2], bf[q4 * 4 + 3], addr);
            }
#pragma unroll
            for (int g = 0; g < 8; ++g)
                mma16816(d[g], a0, a1, a2, a3, bf[g * 2], bf[g * 2 + 1]);
            mma16816(dd, a0, a1, a2, a3, bden, bden);
        }
        if (s < 31) {
#pragma unroll
            for (int k = 0; k < 4; ++k)
                *(uint4*)(smem + nboff + (so + k * 16) * 272 + sjq * 16) = nr[k];
            mr = nmr; mr8 = nmr8;
        }
        __syncthreads();
    }

    // --- epilogue: denominators (col 0 of dd, lanes with lane&3==0), divide, ELU ---
    float den_r  = __shfl_sync(0xffffffffu, dd[0], lane & 28);
    float den_r8 = __shfl_sync(0xffffffffu, dd[2], lane & 28);
    float invr  = 1.0f / den_r;
    float invr8 = 1.0f / den_r8;
    float* o0 = out + (size_t)(i0 + r) * (NM * OUTF) + m * OUTF;
    float* o1 = out + (size_t)(i0 + r + 8) * (NM * OUTF) + m * OUTF;
#pragma unroll
    for (int g = 0; g < 8; ++g) {
        int col = g * 8 + (lane & 3) * 2;
        float2 w0, w1;
        float v;
        v = d[g][0] * invr;  w0.x = v > 0.f ? v : __expf(v) - 1.f;
        v = d[g][1] * invr;  w0.y = v > 0.f ? v : __expf(v) - 1.f;
        v = d[g][2] * invr8; w1.x = v > 0.f ? v : __expf(v) - 1.f;
        v = d[g][3] * invr8; w1.y = v > 0.f ? v : __expf(v) - 1.f;
        *(float2*)&o0[col] = w0;
        *(float2*)&o1[col] = w1;
    }
}

extern "C" void kernel_launch(void* const* d_in, const int* in_sizes, int n_in,
                              void* d_out, int out_size) {
    const float* x   = (const float*)d_in[0];
    const int*   adj = (const int*)d_in[1];
    const float* W   = (const float*)d_in[2];
    const float* a1  = (const float*)d_in[3];
    const float* a2  = (const float*)d_in[4];
    const float* Wc  = (const float*)d_in[5];
    const float* bc  = (const float*)d_in[6];
    float* out = (float*)d_out;

    k_pool<<<64, 256>>>(x);
    k_cond<<<1, 512>>>(Wc, bc);
    k_pack<<<2048, 256>>>(adj);
    k_hgemm<<<dim3(Nn / 64, NM / 2), 256>>>(x, W);
    k_ea<<<NM * Nn / 8, 256>>>(a1, a2);
    k_tr<<<dim3(Nn / 64, NM), 256>>>();
    k_attn<<<dim3(Nn / 128, NM), 256>>>(out);
}